// round 14
// baseline (speedup 1.0000x reference)
#include <cuda_runtime.h>
#include <cuda_bf16.h>
#include <cuda_fp16.h>
#include <math.h>
#include <stdint.h>

// Problem constants
#define Bsz  4
#define Lseq 4096
#define DIMc 1024
#define Hn   16
#define DHc  64
#define NFc  64
#define Mrows (Bsz * Lseq)          // 16384
#define BHc   (Bsz * Hn)            // 64
#define EPSf  1e-6f

// ---------------------------------------------------------------------------
// Scratch (device globals)
// ---------------------------------------------------------------------------
__device__ float g_q[(size_t)Mrows * DIMc];
__device__ float g_k[(size_t)Mrows * DIMc];
__device__ float g_v[(size_t)Mrows * DIMc];
__device__ float g_phi[(size_t)BHc * Lseq * NFc];
__device__ float g_Nt[BHc * DHc * NFc];   // transposed: [bh][d][f]
__device__ float g_D[BHc * NFc];

// bf16 split planes (x for Q/K; Wq, Wk)
__device__ __nv_bfloat16 g_xhi[(size_t)Mrows * DIMc];
__device__ __nv_bfloat16 g_xlo[(size_t)Mrows * DIMc];
__device__ __nv_bfloat16 g_whi[2 * DIMc * DIMc];
__device__ __nv_bfloat16 g_wlo[2 * DIMc * DIMc];
// fp16 planes (x for V; ctx; Wv, Wo single-plane)
__device__ __half g_xh[(size_t)Mrows * DIMc];
__device__ __half g_xl[(size_t)Mrows * DIMc];
__device__ __half g_cth[(size_t)Mrows * DIMc];
__device__ __half g_ctl[(size_t)Mrows * DIMc];
__device__ __half g_wv16[DIMc * DIMc];
__device__ __half g_wo16[DIMc * DIMc];

// ---------------------------------------------------------------------------
// PTX helpers
// ---------------------------------------------------------------------------
__device__ __forceinline__ uint32_t smem_u32(const void* p) {
    uint32_t a;
    asm("{ .reg .u64 t; cvta.to.shared.u64 t, %1; cvt.u32.u64 %0, t; }" : "=r"(a) : "l"(p));
    return a;
}

#define CP16(dst, src) \
    asm volatile("cp.async.cg.shared.global [%0], [%1], 16;" :: "r"(dst), "l"(src))
#define CP_COMMIT() asm volatile("cp.async.commit_group;" ::: "memory")
#define CP_WAIT(n)  asm volatile("cp.async.wait_group %0;" :: "n"(n) : "memory")

__device__ __forceinline__ void ldsm_x4(uint32_t* r, uint32_t addr) {
    asm volatile("ldmatrix.sync.aligned.m8n8.x4.shared.b16 {%0,%1,%2,%3}, [%4];"
        : "=r"(r[0]), "=r"(r[1]), "=r"(r[2]), "=r"(r[3]) : "r"(addr));
}
__device__ __forceinline__ void mma_bf16(float* c, const uint32_t* a, const uint32_t* b) {
    asm volatile(
        "mma.sync.aligned.m16n8k16.row.col.f32.bf16.bf16.f32 "
        "{%0,%1,%2,%3}, {%4,%5,%6,%7}, {%8,%9}, {%0,%1,%2,%3};"
        : "+f"(c[0]), "+f"(c[1]), "+f"(c[2]), "+f"(c[3])
        : "r"(a[0]), "r"(a[1]), "r"(a[2]), "r"(a[3]), "r"(b[0]), "r"(b[1]));
}
__device__ __forceinline__ void mma_f16(float* c, const uint32_t* a, const uint32_t* b) {
    asm volatile(
        "mma.sync.aligned.m16n8k16.row.col.f32.f16.f16.f32 "
        "{%0,%1,%2,%3}, {%4,%5,%6,%7}, {%8,%9}, {%0,%1,%2,%3};"
        : "+f"(c[0]), "+f"(c[1]), "+f"(c[2]), "+f"(c[3])
        : "r"(a[0]), "r"(a[1]), "r"(a[2]), "r"(a[3]), "r"(b[0]), "r"(b[1]));
}

// SMEM tile geometry: b16 rows of 32 elems padded to 40 (80 bytes)
#define ROWB       80
#define A_BYTES    (128 * ROWB)          // 10240
#define B_BYTES    (256 * ROWB)          // 20480
// bf16 3-term kernel stage: Ahi|Alo|Bhi|Blo
#define STG3       (2 * A_BYTES + 2 * B_BYTES)   // 61440
#define GEMM3_SMEM (1024 + 3 * STG3)             // 185344
#define OFF_AHI 0
#define OFF_ALO A_BYTES
#define OFF_BHI (2 * A_BYTES)
#define OFF_BLO (2 * A_BYTES + B_BYTES)
// fp16 2-term kernel stage: Ah|Al|B
#define STG2       (2 * A_BYTES + B_BYTES)       // 40960
#define GEMM2_SMEM (1024 + 3 * STG2)             // 123904
#define OFF2_AH 0
#define OFF2_AL A_BYTES
#define OFF2_B  (2 * A_BYTES)

struct GemmArgs {
    const __nv_bfloat16* whi[2];
    const __nv_bfloat16* wlo[2];
    const float* bias[2];
    float* C[2];
};

// ---------------------------------------------------------------------------
// x split: fp32 -> bf16 hi/lo AND fp16 hi/lo
// ---------------------------------------------------------------------------
__global__ void split_x(const float* __restrict__ src,
                        __nv_bfloat16* __restrict__ bh, __nv_bfloat16* __restrict__ bl,
                        __half* __restrict__ hh, __half* __restrict__ hl, int n4) {
    int i = blockIdx.x * blockDim.x + threadIdx.x;
    if (i >= n4) return;
    float4 v = ((const float4*)src)[i];
    float vv[4] = {v.x, v.y, v.z, v.w};
    __nv_bfloat16 b0[4], b1[4];
    __half h0[4], h1[4];
    #pragma unroll
    for (int e = 0; e < 4; e++) {
        b0[e] = __float2bfloat16(vv[e]);
        b1[e] = __float2bfloat16(vv[e] - __bfloat162float(b0[e]));
        h0[e] = __float2half_rn(vv[e]);
        h1[e] = __float2half_rn(vv[e] - __half2float(h0[e]));
    }
    ((uint2*)bh)[i] = *(uint2*)b0;
    ((uint2*)bl)[i] = *(uint2*)b1;
    ((uint2*)hh)[i] = *(uint2*)h0;
    ((uint2*)hl)[i] = *(uint2*)h1;
}

// W bf16 split (Wq, Wk)
__global__ void split_w(const float* __restrict__ src,
                        __nv_bfloat16* __restrict__ hi,
                        __nv_bfloat16* __restrict__ lo, int n4) {
    int i = blockIdx.x * blockDim.x + threadIdx.x;
    if (i >= n4) return;
    float4 v = ((const float4*)src)[i];
    float vv[4] = {v.x, v.y, v.z, v.w};
    __nv_bfloat16 h[4], l[4];
    #pragma unroll
    for (int e = 0; e < 4; e++) {
        h[e] = __float2bfloat16(vv[e]);
        l[e] = __float2bfloat16(vv[e] - __bfloat162float(h[e]));
    }
    ((uint2*)hi)[i] = *(uint2*)h;
    ((uint2*)lo)[i] = *(uint2*)l;
}

// W single-plane fp16 (Wv, Wo)
__global__ void conv_h(const float* __restrict__ src, __half* __restrict__ dst, int n4) {
    int i = blockIdx.x * blockDim.x + threadIdx.x;
    if (i >= n4) return;
    float4 v = ((const float4*)src)[i];
    __half h[4] = {__float2half_rn(v.x), __float2half_rn(v.y),
                   __float2half_rn(v.z), __float2half_rn(v.w)};
    ((uint2*)dst)[i] = *(uint2*)h;
}

__global__ void init_kernel() {
    int i = blockIdx.x * blockDim.x + threadIdx.x;
    if (i < BHc * DHc * NFc) g_Nt[i] = 0.0f;
    if (i < BHc * NFc)       g_D[i] = 0.0f;
}

// ---------------------------------------------------------------------------
// bf16 3-term GEMM (Q, K): 128x256 tile, BK=32, 3-stage, 256 thr, 2x4 warps.
// ---------------------------------------------------------------------------
__device__ __forceinline__ void issue3(
    uint32_t sbase, int t,
    const __nv_bfloat16* __restrict__ Ahi, const __nv_bfloat16* __restrict__ Alo,
    const __nv_bfloat16* __restrict__ Whi, const __nv_bfloat16* __restrict__ Wlo,
    int bm, int nLoc, int kOff)
{
    #pragma unroll
    for (int j = 0; j < 12; j++) {
        int idx = t + j * 256;
        int r = idx >> 2, c = idx & 3;
        uint32_t so;
        const __nv_bfloat16* src;
        if (r < 256) {
            int rr = r & 127;
            so = (uint32_t)((r < 128 ? OFF_AHI : OFF_ALO) + rr * ROWB + c * 16);
            src = (r < 128 ? Ahi : Alo) + (size_t)(bm + rr) * DIMc + kOff + c * 8;
        } else {
            int rb = r - 256;
            int rr = rb & 255;
            so = (uint32_t)((rb < 256 ? OFF_BHI : OFF_BLO) + rr * ROWB + c * 16);
            src = (rb < 256 ? Whi : Wlo) + (size_t)(nLoc + rr) * DIMc + kOff + c * 8;
        }
        CP16(sbase + so, src);
    }
    CP_COMMIT();
}

__global__ void __launch_bounds__(256, 1) gemm_bf3(
    const __nv_bfloat16* __restrict__ Ahi, const __nv_bfloat16* __restrict__ Alo,
    GemmArgs args)
{
    extern __shared__ __align__(16) char sm[];
    float* sbias = (float*)sm;
    uint32_t sb = smem_u32(sm) + 1024;

    int t = threadIdx.x;
    int wid = t >> 5, lane = t & 31;
    int warp_m = wid >> 2, warp_n = wid & 3;
    int bm = blockIdx.y << 7;
    int wsel = blockIdx.x >> 2;
    int nLoc = (blockIdx.x & 3) << 8;

    const __nv_bfloat16* Whi = args.whi[wsel];
    const __nv_bfloat16* Wlo = args.wlo[wsel];
    float* C = args.C[wsel];

    if (t < 256) sbias[t] = args.bias[wsel][nLoc + t];

    float acc[4][8][4];
    #pragma unroll
    for (int mi = 0; mi < 4; mi++)
        #pragma unroll
        for (int ni = 0; ni < 8; ni++)
            #pragma unroll
            for (int e = 0; e < 4; e++) acc[mi][ni][e] = 0.0f;

    uint32_t aoff = (uint32_t)((warp_m * 64 + (lane & 15)) * ROWB + (lane >> 4) * 16);
    uint32_t bpair = (uint32_t)((warp_n * 64 + (lane >> 4) * 8 + (lane & 7)) * ROWB
                                + ((lane >> 3) & 1) * 16);

    issue3(sb + 0 * STG3, t, Ahi, Alo, Whi, Wlo, bm, nLoc, 0);
    issue3(sb + 1 * STG3, t, Ahi, Alo, Whi, Wlo, bm, nLoc, 32);

    #pragma unroll 1
    for (int ch = 0; ch < 32; ch++) {
        CP_WAIT(1);
        __syncthreads();
        if (ch + 2 < 32)
            issue3(sb + ((ch + 2) % 3) * STG3, t, Ahi, Alo, Whi, Wlo, bm, nLoc, (ch + 2) * 32);
        uint32_t stg = sb + (ch % 3) * STG3;
        #pragma unroll
        for (int ks = 0; ks < 2; ks++) {
            uint32_t ahi[4][4], alo[4][4], bhi[8][2], blo[8][2];
            #pragma unroll
            for (int mi = 0; mi < 4; mi++) {
                uint32_t a = stg + aoff + (uint32_t)(mi * 16 * ROWB + ks * 32);
                ldsm_x4(ahi[mi], a + OFF_AHI);
                ldsm_x4(alo[mi], a + OFF_ALO);
            }
            #pragma unroll
            for (int pni = 0; pni < 8; pni += 2) {
                uint32_t tmp[4];
                uint32_t b = stg + bpair + (uint32_t)(pni * 8 * ROWB + ks * 32);
                ldsm_x4(tmp, b + OFF_BHI);
                bhi[pni][0] = tmp[0]; bhi[pni][1] = tmp[1];
                bhi[pni + 1][0] = tmp[2]; bhi[pni + 1][1] = tmp[3];
                ldsm_x4(tmp, b + OFF_BLO);
                blo[pni][0] = tmp[0]; blo[pni][1] = tmp[1];
                blo[pni + 1][0] = tmp[2]; blo[pni + 1][1] = tmp[3];
            }
            #pragma unroll
            for (int mi = 0; mi < 4; mi++)
                #pragma unroll
                for (int ni = 0; ni < 8; ni++) {
                    mma_bf16(acc[mi][ni], ahi[mi], bhi[ni]);
                    mma_bf16(acc[mi][ni], ahi[mi], blo[ni]);
                    mma_bf16(acc[mi][ni], alo[mi], bhi[ni]);
                }
        }
        __syncthreads();
    }

    #pragma unroll
    for (int mi = 0; mi < 4; mi++) {
        int row0 = bm + warp_m * 64 + mi * 16 + (lane >> 2);
        #pragma unroll
        for (int ni = 0; ni < 8; ni++) {
            int col = warp_n * 64 + ni * 8 + (lane & 3) * 2;
            float b0 = sbias[col], b1 = sbias[col + 1];
            float2 o0 = make_float2(acc[mi][ni][0] + b0, acc[mi][ni][1] + b1);
            float2 o1 = make_float2(acc[mi][ni][2] + b0, acc[mi][ni][3] + b1);
            *(float2*)(C + (size_t)row0 * DIMc + nLoc + col) = o0;
            *(float2*)(C + (size_t)(row0 + 8) * DIMc + nLoc + col) = o1;
        }
    }
}

// ---------------------------------------------------------------------------
// fp16 2-term asymmetric GEMM (V, OUT): A = (hi, lo) fp16, W = single fp16.
// 128x256 tile, BK=32, 3-stage, 256 thr, 2x4 warps, 2 MMAs per tile pair.
// ---------------------------------------------------------------------------
__device__ __forceinline__ void issue2(
    uint32_t sbase, int t,
    const __half* __restrict__ Ah, const __half* __restrict__ Al,
    const __half* __restrict__ W, int bm, int nLoc, int kOff)
{
    #pragma unroll
    for (int j = 0; j < 8; j++) {
        int idx = t + j * 256;
        int r = idx >> 2, c = idx & 3;
        uint32_t so;
        const __half* src;
        if (r < 128)      { so = OFF2_AH; int rr = r;       src = Ah + (size_t)(bm + rr) * DIMc; so += (uint32_t)(rr * ROWB + c * 16); }
        else if (r < 256) { so = OFF2_AL; int rr = r - 128; src = Al + (size_t)(bm + rr) * DIMc; so += (uint32_t)(rr * ROWB + c * 16); }
        else              { so = OFF2_B;  int rr = r - 256; src = W  + (size_t)(nLoc + rr) * DIMc; so += (uint32_t)(rr * ROWB + c * 16); }
        CP16(sbase + so, src + kOff + c * 8);
    }
    CP_COMMIT();
}

__global__ void __launch_bounds__(256, 1) gemm_h2(
    const __half* __restrict__ Ah, const __half* __restrict__ Al,
    const __half* __restrict__ W, const float* __restrict__ bias,
    float* __restrict__ C)
{
    extern __shared__ __align__(16) char sm[];
    float* sbias = (float*)sm;
    uint32_t sb = smem_u32(sm) + 1024;

    int t = threadIdx.x;
    int wid = t >> 5, lane = t & 31;
    int warp_m = wid >> 2, warp_n = wid & 3;
    int bm = blockIdx.y << 7;
    int nLoc = blockIdx.x << 8;

    if (t < 256) sbias[t] = bias[nLoc + t];

    float acc[4][8][4];
    #pragma unroll
    for (int mi = 0; mi < 4; mi++)
        #pragma unroll
        for (int ni = 0; ni < 8; ni++)
            #pragma unroll
            for (int e = 0; e < 4; e++) acc[mi][ni][e] = 0.0f;

    uint32_t aoff = (uint32_t)((warp_m * 64 + (lane & 15)) * ROWB + (lane >> 4) * 16);
    uint32_t bpair = (uint32_t)((warp_n * 64 + (lane >> 4) * 8 + (lane & 7)) * ROWB
                                + ((lane >> 3) & 1) * 16);

    issue2(sb + 0 * STG2, t, Ah, Al, W, bm, nLoc, 0);
    issue2(sb + 1 * STG2, t, Ah, Al, W, bm, nLoc, 32);

    #pragma unroll 1
    for (int ch = 0; ch < 32; ch++) {
        CP_WAIT(1);
        __syncthreads();
        if (ch + 2 < 32)
            issue2(sb + ((ch + 2) % 3) * STG2, t, Ah, Al, W, bm, nLoc, (ch + 2) * 32);
        uint32_t stg = sb + (ch % 3) * STG2;
        #pragma unroll
        for (int ks = 0; ks < 2; ks++) {
            uint32_t ah[4][4], al[4][4], bb[8][2];
            #pragma unroll
            for (int mi = 0; mi < 4; mi++) {
                uint32_t a = stg + aoff + (uint32_t)(mi * 16 * ROWB + ks * 32);
                ldsm_x4(ah[mi], a + OFF2_AH);
                ldsm_x4(al[mi], a + OFF2_AL);
            }
            #pragma unroll
            for (int pni = 0; pni < 8; pni += 2) {
                uint32_t tmp[4];
                uint32_t b = stg + bpair + (uint32_t)(pni * 8 * ROWB + ks * 32);
                ldsm_x4(tmp, b + OFF2_B);
                bb[pni][0] = tmp[0]; bb[pni][1] = tmp[1];
                bb[pni + 1][0] = tmp[2]; bb[pni + 1][1] = tmp[3];
            }
            #pragma unroll
            for (int mi = 0; mi < 4; mi++)
                #pragma unroll
                for (int ni = 0; ni < 8; ni++) {
                    mma_f16(acc[mi][ni], ah[mi], bb[ni]);
                    mma_f16(acc[mi][ni], al[mi], bb[ni]);
                }
        }
        __syncthreads();
    }

    #pragma unroll
    for (int mi = 0; mi < 4; mi++) {
        int row0 = bm + warp_m * 64 + mi * 16 + (lane >> 2);
        #pragma unroll
        for (int ni = 0; ni < 8; ni++) {
            int col = warp_n * 64 + ni * 8 + (lane & 3) * 2;
            float b0 = sbias[col], b1 = sbias[col + 1];
            float2 o0 = make_float2(acc[mi][ni][0] + b0, acc[mi][ni][1] + b1);
            float2 o1 = make_float2(acc[mi][ni][2] + b0, acc[mi][ni][3] + b1);
            *(float2*)(C + (size_t)row0 * DIMc + nLoc + col) = o0;
            *(float2*)(C + (size_t)(row0 + 8) * DIMc + nLoc + col) = o1;
        }
    }
}

// ---------------------------------------------------------------------------
// Fused feature kernel: db-outer loop hoists W0 into registers.
// ---------------------------------------------------------------------------
#define W0P 68
#define FEAT_SMEM ((W0P * 64 + 4 * 64 * 64) * 4)   // 82,688 B

__global__ void __launch_bounds__(256) feature_kernel(const float* __restrict__ Wrf) {
    extern __shared__ float fs[];
    float* W0t = fs;
    float* ks  = fs + W0P * 64;
    float* qs  = ks + 4096;
    float* Vs  = qs + 4096;
    float* Es  = Vs + 4096;

    int bh = blockIdx.y;
    int b = bh >> 4, h = bh & 15;
    int l0 = blockIdx.x * 64;
    int t = threadIdx.x;

    for (int e = t; e < 4096; e += 256) {
        int d = e >> 6, f = e & 63;
        W0t[f * W0P + d] = Wrf[h * 4096 + e];
    }
    for (int e = t; e < 1024; e += 256) {
        int row = e >> 4, c4 = (e & 15) << 2;
        size_t g = (size_t)(b * Lseq + l0 + row) * DIMc + h * DHc + c4;
        *(float4*)(ks + row * 64 + c4) = *(const float4*)(g_k + g);
        *(float4*)(qs + row * 64 + c4) = *(const float4*)(g_q + g);
        *(float4*)(Vs + row * 64 + c4) = *(const float4*)(g_v + g);
    }
    __syncthreads();

    int warp = t >> 5, lane = t & 31;
    const float* w0p = W0t + lane * W0P;
    const float* w1p = W0t + (lane + 32) * W0P;
    int lb = warp * 8;

    float aK0[8], aK1[8], aQ0[8], aQ1[8], kk[8];
    #pragma unroll
    for (int r = 0; r < 8; r++) {
        aK0[r] = aK1[r] = aQ0[r] = aQ1[r] = kk[r] = 0.f;
    }

    #pragma unroll
    for (int db = 0; db < 16; db++) {
        float4 w0 = *(const float4*)(w0p + db * 4);
        float4 w1 = *(const float4*)(w1p + db * 4);
        #pragma unroll
        for (int r = 0; r < 8; r++) {
            float4 kv = *(const float4*)(ks + (lb + r) * 64 + db * 4);
            float4 qv = *(const float4*)(qs + (lb + r) * 64 + db * 4);
            aK0[r] = fmaf(kv.x, w0.x, aK0[r]); aK0[r] = fmaf(kv.y, w0.y, aK0[r]);
            aK0[r] = fmaf(kv.z, w0.z, aK0[r]); aK0[r] = fmaf(kv.w, w0.w, aK0[r]);
            aK1[r] = fmaf(kv.x, w1.x, aK1[r]); aK1[r] = fmaf(kv.y, w1.y, aK1[r]);
            aK1[r] = fmaf(kv.z, w1.z, aK1[r]); aK1[r] = fmaf(kv.w, w1.w, aK1[r]);
            aQ0[r] = fmaf(qv.x, w0.x, aQ0[r]); aQ0[r] = fmaf(qv.y, w0.y, aQ0[r]);
            aQ0[r] = fmaf(qv.z, w0.z, aQ0[r]); aQ0[r] = fmaf(qv.w, w0.w, aQ0[r]);
            aQ1[r] = fmaf(qv.x, w1.x, aQ1[r]); aQ1[r] = fmaf(qv.y, w1.y, aQ1[r]);
            aQ1[r] = fmaf(qv.z, w1.z, aQ1[r]); aQ1[r] = fmaf(qv.w, w1.w, aQ1[r]);
            kk[r]  = fmaf(kv.x, kv.x, kk[r]);  kk[r]  = fmaf(kv.y, kv.y, kk[r]);
            kk[r]  = fmaf(kv.z, kv.z, kk[r]);  kk[r]  = fmaf(kv.w, kv.w, kk[r]);
        }
    }

    #pragma unroll 1
    for (int r = 0; r < 8; r++) {
        int l = lb + r;
        float hk = 0.5f * kk[r];
        Es[l * 64 + lane]      = __expf(aK0[r] - hk);
        Es[l * 64 + lane + 32] = __expf(aK1[r] - hk);

        float e0 = __expf(aQ0[r]), e1 = __expf(aQ1[r]);
        float s = e0 + e1;
        #pragma unroll
        for (int o = 16; o > 0; o >>= 1)
            s += __shfl_xor_sync(0xffffffffu, s, o);
        float inv = 1.0f / s;
        size_t base = ((size_t)bh * Lseq + l0 + l) * NFc;
        g_phi[base + lane]      = e0 * inv;
        g_phi[base + lane + 32] = e1 * inv;
    }
    __syncthreads();

    int tf = (t >> 4) << 2;
    int td = (t & 15) << 2;
    float acc[4][4];
    #pragma unroll
    for (int i = 0; i < 4; i++)
        #pragma unroll
        for (int j = 0; j < 4; j++) acc[i][j] = 0.0f;
    float dacc[4] = {0.f, 0.f, 0.f, 0.f};

    #pragma unroll 4
    for (int l = 0; l < 64; l++) {
        float4 a  = *(const float4*)(Es + l * 64 + tf);
        float4 b4 = *(const float4*)(Vs + l * 64 + td);
        float av[4] = {a.x, a.y, a.z, a.w};
        float bv[4] = {b4.x, b4.y, b4.z, b4.w};
        #pragma unroll
        for (int i = 0; i < 4; i++)
            #pragma unroll
            for (int j = 0; j < 4; j++)
                acc[i][j] = fmaf(av[i], bv[j], acc[i][j]);
        if (td == 0) {
            #pragma unroll
            for (int i = 0; i < 4; i++) dacc[i] += av[i];
        }
    }

    #pragma unroll
    for (int i = 0; i < 4; i++)
        #pragma unroll
        for (int j = 0; j < 4; j++)
            atomicAdd(&g_Nt[bh * (DHc * NFc) + (td + j) * NFc + tf + i], acc[i][j]);
    if (td == 0) {
        #pragma unroll
        for (int i = 0; i < 4; i++)
            atomicAdd(&g_D[bh * NFc + tf + i], dacc[i]);
    }
}

// ---------------------------------------------------------------------------
// Combine: j-outer / r-inner (N cols in regs); writes ctx fp16 hi/lo planes.
// ---------------------------------------------------------------------------
__global__ void __launch_bounds__(256) combine_kernel() {
    int bh = blockIdx.y;
    int b = bh >> 4, h = bh & 15;
    int l0 = blockIdx.x * 64;

    __shared__ float Nts[64 * W0P];
    __shared__ float Ds[NFc];
    __shared__ float sSE;

    int t = threadIdx.x;
    for (int e = t; e < 4096; e += 256) {
        int d = e >> 6, f = e & 63;
        Nts[d * W0P + f] = g_Nt[bh * (DHc * NFc) + e];
    }
    if (t < NFc) Ds[t] = g_D[bh * NFc + t];
    __syncthreads();
    if (t == 0) {
        float s = 0.f;
        #pragma unroll
        for (int f = 0; f < NFc; f++) s += Ds[f];
        sSE = s * EPSf;
    }
    __syncthreads();

    int warp = t >> 5, lane = t & 31;
    const float* n0p = Nts + lane * W0P;
    const float* n1p = Nts + (lane + 32) * W0P;
    size_t lbase = (size_t)bh * Lseq + l0 + warp * 8;

    float num0[8], num1[8], den[8];
    #pragma unroll
    for (int r = 0; r < 8; r++) { num0[r] = num1[r] = den[r] = 0.f; }

    #pragma unroll 4
    for (int j = 0; j < 16; j++) {
        float4 n0 = *(const float4*)(n0p + j * 4);
        float4 n1 = *(const float4*)(n1p + j * 4);
        float4 dd = *(const float4*)(Ds + j * 4);
        #pragma unroll
        for (int r = 0; r < 8; r++) {
            float4 p = *(const float4*)(g_phi + (lbase + r) * NFc + j * 4);
            num0[r] = fmaf(p.x, n0.x, num0[r]); num0[r] = fmaf(p.y, n0.y, num0[r]);
            num0[r] = fmaf(p.z, n0.z, num0[r]); num0[r] = fmaf(p.w, n0.w, num0[r]);
            num1[r] = fmaf(p.x, n1.x, num1[r]); num1[r] = fmaf(p.y, n1.y, num1[r]);
            num1[r] = fmaf(p.z, n1.z, num1[r]); num1[r] = fmaf(p.w, n1.w, num1[r]);
            den[r]  = fmaf(p.x, dd.x, den[r]);  den[r]  = fmaf(p.y, dd.y, den[r]);
            den[r]  = fmaf(p.z, dd.z, den[r]);  den[r]  = fmaf(p.w, dd.w, den[r]);
        }
    }

    #pragma unroll
    for (int r = 0; r < 8; r++) {
        int l = l0 + warp * 8 + r;
        float invd = 1.0f / (den[r] + sSE);
        float v0 = num0[r] * invd;
        float v1 = num1[r] * invd;
        size_t g = (size_t)(b * Lseq + l) * DIMc + h * DHc;
        __half h0 = __float2half_rn(v0);
        __half h1 = __float2half_rn(v1);
        g_cth[g + lane]      = h0;
        g_cth[g + lane + 32] = h1;
        g_ctl[g + lane]      = __float2half_rn(v0 - __half2float(h0));
        g_ctl[g + lane + 32] = __float2half_rn(v1 - __half2float(h1));
    }
}

// ---------------------------------------------------------------------------
// Launch
// ---------------------------------------------------------------------------
extern "C" void kernel_launch(void* const* d_in, const int* in_sizes, int n_in,
                              void* d_out, int out_size) {
    const float* x   = (const float*)d_in[0];
    const float* Wq  = (const float*)d_in[1];
    const float* bq  = (const float*)d_in[2];
    const float* Wk  = (const float*)d_in[3];
    const float* bk  = (const float*)d_in[4];
    const float* Wv  = (const float*)d_in[5];
    const float* bv  = (const float*)d_in[6];
    const float* Wo  = (const float*)d_in[7];
    const float* bo  = (const float*)d_in[8];
    const float* Wrf = (const float*)d_in[9];
    float* out = (float*)d_out;

    float *q, *k, *v;
    __nv_bfloat16 *xhi, *xlo, *whi, *wlo;
    __half *xh, *xl, *cth, *ctl, *wv16, *wo16;
    cudaGetSymbolAddress((void**)&q,    g_q);
    cudaGetSymbolAddress((void**)&k,    g_k);
    cudaGetSymbolAddress((void**)&v,    g_v);
    cudaGetSymbolAddress((void**)&xhi,  g_xhi);
    cudaGetSymbolAddress((void**)&xlo,  g_xlo);
    cudaGetSymbolAddress((void**)&whi,  g_whi);
    cudaGetSymbolAddress((void**)&wlo,  g_wlo);
    cudaGetSymbolAddress((void**)&xh,   g_xh);
    cudaGetSymbolAddress((void**)&xl,   g_xl);
    cudaGetSymbolAddress((void**)&cth,  g_cth);
    cudaGetSymbolAddress((void**)&ctl,  g_ctl);
    cudaGetSymbolAddress((void**)&wv16, g_wv16);
    cudaGetSymbolAddress((void**)&wo16, g_wo16);

    cudaFuncSetAttribute(gemm_bf3, cudaFuncAttributeMaxDynamicSharedMemorySize, GEMM3_SMEM);
    cudaFuncSetAttribute(gemm_h2,  cudaFuncAttributeMaxDynamicSharedMemorySize, GEMM2_SMEM);
    cudaFuncSetAttribute(feature_kernel, cudaFuncAttributeMaxDynamicSharedMemorySize, FEAT_SMEM);

    const size_t WN = (size_t)DIMc * DIMc;
    const int xn4 = (int)(((size_t)Mrows * DIMc) / 4);
    const int wn4 = (int)(WN / 4);

    split_x<<<(xn4 + 255) / 256, 256>>>(x, xhi, xlo, xh, xl, xn4);
    split_w<<<(wn4 + 255) / 256, 256>>>(Wq, whi + 0 * WN, wlo + 0 * WN, wn4);
    split_w<<<(wn4 + 255) / 256, 256>>>(Wk, whi + 1 * WN, wlo + 1 * WN, wn4);
    conv_h<<<(wn4 + 255) / 256, 256>>>(Wv, wv16, wn4);
    conv_h<<<(wn4 + 255) / 256, 256>>>(Wo, wo16, wn4);

    init_kernel<<<(BHc * DHc * NFc + 255) / 256, 256>>>();

    // Q, K projections (bf16 3-term), fused: grid.x = 2 weights x 4 N-blocks
    {
        GemmArgs a;
        a.whi[0] = whi + 0 * WN; a.whi[1] = whi + 1 * WN;
        a.wlo[0] = wlo + 0 * WN; a.wlo[1] = wlo + 1 * WN;
        a.bias[0] = bq; a.bias[1] = bk;
        a.C[0] = q; a.C[1] = k;
        gemm_bf3<<<dim3(8, Mrows / 128), 256, GEMM3_SMEM>>>(xhi, xlo, a);
    }
    // V projection (fp16 2-term asym)
    gemm_h2<<<dim3(4, Mrows / 128), 256, GEMM2_SMEM>>>(xh, xl, wv16, bv, v);

    feature_kernel<<<dim3(Lseq / 64, BHc), 256, FEAT_SMEM>>>(Wrf);
    combine_kernel<<<dim3(Lseq / 64, BHc), 256>>>();

    // Output GEMM (fp16 2-term asym)
    gemm_h2<<<dim3(4, Mrows / 128), 256, GEMM2_SMEM>>>(cth, ctl, wo16, bo, out);
}

// round 15
// speedup vs baseline: 1.0062x; 1.0062x over previous
#include <cuda_runtime.h>
#include <cuda_bf16.h>
#include <cuda_fp16.h>
#include <math.h>
#include <stdint.h>

// Problem constants
#define Bsz  4
#define Lseq 4096
#define DIMc 1024
#define Hn   16
#define DHc  64
#define NFc  64
#define Mrows (Bsz * Lseq)          // 16384
#define BHc   (Bsz * Hn)            // 64
#define EPSf  1e-6f

// ---------------------------------------------------------------------------
// Scratch (device globals)
// ---------------------------------------------------------------------------
__device__ float g_q[(size_t)Mrows * DIMc];
__device__ float g_k[(size_t)Mrows * DIMc];
__device__ float g_v[(size_t)Mrows * DIMc];
__device__ float g_phi[(size_t)BHc * Lseq * NFc];
__device__ float g_Nt[BHc * DHc * NFc];   // transposed: [bh][d][f]
__device__ float g_D[BHc * NFc];

// bf16 split planes (x for Q/K; Wq, Wk)
__device__ __nv_bfloat16 g_xhi[(size_t)Mrows * DIMc];
__device__ __nv_bfloat16 g_xlo[(size_t)Mrows * DIMc];
__device__ __nv_bfloat16 g_whi[2 * DIMc * DIMc];
__device__ __nv_bfloat16 g_wlo[2 * DIMc * DIMc];
// fp16 planes (x for V; ctx; Wv, Wo single-plane)
__device__ __half g_xh[(size_t)Mrows * DIMc];
__device__ __half g_xl[(size_t)Mrows * DIMc];
__device__ __half g_cth[(size_t)Mrows * DIMc];
__device__ __half g_ctl[(size_t)Mrows * DIMc];
__device__ __half g_wv16[DIMc * DIMc];
__device__ __half g_wo16[DIMc * DIMc];

// ---------------------------------------------------------------------------
// PTX helpers
// ---------------------------------------------------------------------------
__device__ __forceinline__ uint32_t smem_u32(const void* p) {
    uint32_t a;
    asm("{ .reg .u64 t; cvta.to.shared.u64 t, %1; cvt.u32.u64 %0, t; }" : "=r"(a) : "l"(p));
    return a;
}

#define CP16(dst, src) \
    asm volatile("cp.async.cg.shared.global [%0], [%1], 16;" :: "r"(dst), "l"(src))
#define CP_COMMIT() asm volatile("cp.async.commit_group;" ::: "memory")
#define CP_WAIT(n)  asm volatile("cp.async.wait_group %0;" :: "n"(n) : "memory")

__device__ __forceinline__ void ldsm_x4(uint32_t* r, uint32_t addr) {
    asm volatile("ldmatrix.sync.aligned.m8n8.x4.shared.b16 {%0,%1,%2,%3}, [%4];"
        : "=r"(r[0]), "=r"(r[1]), "=r"(r[2]), "=r"(r[3]) : "r"(addr));
}
__device__ __forceinline__ void mma_bf16(float* c, const uint32_t* a, const uint32_t* b) {
    asm volatile(
        "mma.sync.aligned.m16n8k16.row.col.f32.bf16.bf16.f32 "
        "{%0,%1,%2,%3}, {%4,%5,%6,%7}, {%8,%9}, {%0,%1,%2,%3};"
        : "+f"(c[0]), "+f"(c[1]), "+f"(c[2]), "+f"(c[3])
        : "r"(a[0]), "r"(a[1]), "r"(a[2]), "r"(a[3]), "r"(b[0]), "r"(b[1]));
}
__device__ __forceinline__ void mma_f16(float* c, const uint32_t* a, const uint32_t* b) {
    asm volatile(
        "mma.sync.aligned.m16n8k16.row.col.f32.f16.f16.f32 "
        "{%0,%1,%2,%3}, {%4,%5,%6,%7}, {%8,%9}, {%0,%1,%2,%3};"
        : "+f"(c[0]), "+f"(c[1]), "+f"(c[2]), "+f"(c[3])
        : "r"(a[0]), "r"(a[1]), "r"(a[2]), "r"(a[3]), "r"(b[0]), "r"(b[1]));
}

// SMEM tile geometry: b16 rows of 32 elems padded to 40 (80 bytes)
#define ROWB       80
#define A_BYTES    (128 * ROWB)          // 10240
#define B_BYTES    (256 * ROWB)          // 20480
// bf16 3-term kernel stage: Ahi|Alo|Bhi|Blo
#define STG3       (2 * A_BYTES + 2 * B_BYTES)   // 61440
#define GEMM3_SMEM (1024 + 3 * STG3)             // 185344
#define OFF_AHI 0
#define OFF_ALO A_BYTES
#define OFF_BHI (2 * A_BYTES)
#define OFF_BLO (2 * A_BYTES + B_BYTES)
// fp16 2-term kernel stage: Ah|Al|B
#define STG2       (2 * A_BYTES + B_BYTES)       // 40960
#define GEMM2_SMEM (1024 + 3 * STG2)             // 123904
#define OFF2_AH 0
#define OFF2_AL A_BYTES
#define OFF2_B  (2 * A_BYTES)

struct GemmArgs {
    const __nv_bfloat16* whi[2];
    const __nv_bfloat16* wlo[2];
    const float* bias[2];
    float* C[2];
};

// ---------------------------------------------------------------------------
// x split: fp32 -> bf16 hi/lo AND fp16 hi/lo
// ---------------------------------------------------------------------------
__global__ void split_x(const float* __restrict__ src,
                        __nv_bfloat16* __restrict__ bh, __nv_bfloat16* __restrict__ bl,
                        __half* __restrict__ hh, __half* __restrict__ hl, int n4) {
    int i = blockIdx.x * blockDim.x + threadIdx.x;
    if (i >= n4) return;
    float4 v = ((const float4*)src)[i];
    float vv[4] = {v.x, v.y, v.z, v.w};
    __nv_bfloat16 b0[4], b1[4];
    __half h0[4], h1[4];
    #pragma unroll
    for (int e = 0; e < 4; e++) {
        b0[e] = __float2bfloat16(vv[e]);
        b1[e] = __float2bfloat16(vv[e] - __bfloat162float(b0[e]));
        h0[e] = __float2half_rn(vv[e]);
        h1[e] = __float2half_rn(vv[e] - __half2float(h0[e]));
    }
    ((uint2*)bh)[i] = *(uint2*)b0;
    ((uint2*)bl)[i] = *(uint2*)b1;
    ((uint2*)hh)[i] = *(uint2*)h0;
    ((uint2*)hl)[i] = *(uint2*)h1;
}

// W bf16 split (Wq, Wk)
__global__ void split_w(const float* __restrict__ src,
                        __nv_bfloat16* __restrict__ hi,
                        __nv_bfloat16* __restrict__ lo, int n4) {
    int i = blockIdx.x * blockDim.x + threadIdx.x;
    if (i >= n4) return;
    float4 v = ((const float4*)src)[i];
    float vv[4] = {v.x, v.y, v.z, v.w};
    __nv_bfloat16 h[4], l[4];
    #pragma unroll
    for (int e = 0; e < 4; e++) {
        h[e] = __float2bfloat16(vv[e]);
        l[e] = __float2bfloat16(vv[e] - __bfloat162float(h[e]));
    }
    ((uint2*)hi)[i] = *(uint2*)h;
    ((uint2*)lo)[i] = *(uint2*)l;
}

// W single-plane fp16 (Wv, Wo)
__global__ void conv_h(const float* __restrict__ src, __half* __restrict__ dst, int n4) {
    int i = blockIdx.x * blockDim.x + threadIdx.x;
    if (i >= n4) return;
    float4 v = ((const float4*)src)[i];
    __half h[4] = {__float2half_rn(v.x), __float2half_rn(v.y),
                   __float2half_rn(v.z), __float2half_rn(v.w)};
    ((uint2*)dst)[i] = *(uint2*)h;
}

__global__ void init_kernel() {
    int i = blockIdx.x * blockDim.x + threadIdx.x;
    if (i < BHc * DHc * NFc) g_Nt[i] = 0.0f;
    if (i < BHc * NFc)       g_D[i] = 0.0f;
}

// ---------------------------------------------------------------------------
// bf16 3-term GEMM (Q, K): 128x256 tile, BK=32, 3-stage, 256 thr, 2x4 warps.
// ---------------------------------------------------------------------------
__device__ __forceinline__ void issue3(
    uint32_t sbase, int t,
    const __nv_bfloat16* __restrict__ Ahi, const __nv_bfloat16* __restrict__ Alo,
    const __nv_bfloat16* __restrict__ Whi, const __nv_bfloat16* __restrict__ Wlo,
    int bm, int nLoc, int kOff)
{
    #pragma unroll
    for (int j = 0; j < 12; j++) {
        int idx = t + j * 256;
        int r = idx >> 2, c = idx & 3;
        uint32_t so;
        const __nv_bfloat16* src;
        if (r < 256) {
            int rr = r & 127;
            so = (uint32_t)((r < 128 ? OFF_AHI : OFF_ALO) + rr * ROWB + c * 16);
            src = (r < 128 ? Ahi : Alo) + (size_t)(bm + rr) * DIMc + kOff + c * 8;
        } else {
            int rb = r - 256;
            int rr = rb & 255;
            so = (uint32_t)((rb < 256 ? OFF_BHI : OFF_BLO) + rr * ROWB + c * 16);
            src = (rb < 256 ? Whi : Wlo) + (size_t)(nLoc + rr) * DIMc + kOff + c * 8;
        }
        CP16(sbase + so, src);
    }
    CP_COMMIT();
}

__global__ void __launch_bounds__(256, 1) gemm_bf3(
    const __nv_bfloat16* __restrict__ Ahi, const __nv_bfloat16* __restrict__ Alo,
    GemmArgs args)
{
    extern __shared__ __align__(16) char sm[];
    float* sbias = (float*)sm;
    uint32_t sb = smem_u32(sm) + 1024;

    int t = threadIdx.x;
    int wid = t >> 5, lane = t & 31;
    int warp_m = wid >> 2, warp_n = wid & 3;
    int bm = blockIdx.y << 7;
    int wsel = blockIdx.x >> 2;
    int nLoc = (blockIdx.x & 3) << 8;

    const __nv_bfloat16* Whi = args.whi[wsel];
    const __nv_bfloat16* Wlo = args.wlo[wsel];
    float* C = args.C[wsel];

    if (t < 256) sbias[t] = args.bias[wsel][nLoc + t];

    float acc[4][8][4];
    #pragma unroll
    for (int mi = 0; mi < 4; mi++)
        #pragma unroll
        for (int ni = 0; ni < 8; ni++)
            #pragma unroll
            for (int e = 0; e < 4; e++) acc[mi][ni][e] = 0.0f;

    uint32_t aoff = (uint32_t)((warp_m * 64 + (lane & 15)) * ROWB + (lane >> 4) * 16);
    uint32_t bpair = (uint32_t)((warp_n * 64 + (lane >> 4) * 8 + (lane & 7)) * ROWB
                                + ((lane >> 3) & 1) * 16);

    issue3(sb + 0 * STG3, t, Ahi, Alo, Whi, Wlo, bm, nLoc, 0);
    issue3(sb + 1 * STG3, t, Ahi, Alo, Whi, Wlo, bm, nLoc, 32);

    #pragma unroll 1
    for (int ch = 0; ch < 32; ch++) {
        CP_WAIT(1);
        __syncthreads();
        if (ch + 2 < 32)
            issue3(sb + ((ch + 2) % 3) * STG3, t, Ahi, Alo, Whi, Wlo, bm, nLoc, (ch + 2) * 32);
        uint32_t stg = sb + (ch % 3) * STG3;
        #pragma unroll
        for (int ks = 0; ks < 2; ks++) {
            uint32_t ahi[4][4], alo[4][4], bhi[8][2], blo[8][2];
            #pragma unroll
            for (int mi = 0; mi < 4; mi++) {
                uint32_t a = stg + aoff + (uint32_t)(mi * 16 * ROWB + ks * 32);
                ldsm_x4(ahi[mi], a + OFF_AHI);
                ldsm_x4(alo[mi], a + OFF_ALO);
            }
            #pragma unroll
            for (int pni = 0; pni < 8; pni += 2) {
                uint32_t tmp[4];
                uint32_t b = stg + bpair + (uint32_t)(pni * 8 * ROWB + ks * 32);
                ldsm_x4(tmp, b + OFF_BHI);
                bhi[pni][0] = tmp[0]; bhi[pni][1] = tmp[1];
                bhi[pni + 1][0] = tmp[2]; bhi[pni + 1][1] = tmp[3];
                ldsm_x4(tmp, b + OFF_BLO);
                blo[pni][0] = tmp[0]; blo[pni][1] = tmp[1];
                blo[pni + 1][0] = tmp[2]; blo[pni + 1][1] = tmp[3];
            }
            #pragma unroll
            for (int mi = 0; mi < 4; mi++)
                #pragma unroll
                for (int ni = 0; ni < 8; ni++) {
                    mma_bf16(acc[mi][ni], ahi[mi], bhi[ni]);
                    mma_bf16(acc[mi][ni], ahi[mi], blo[ni]);
                    mma_bf16(acc[mi][ni], alo[mi], bhi[ni]);
                }
        }
        __syncthreads();
    }

    #pragma unroll
    for (int mi = 0; mi < 4; mi++) {
        int row0 = bm + warp_m * 64 + mi * 16 + (lane >> 2);
        #pragma unroll
        for (int ni = 0; ni < 8; ni++) {
            int col = warp_n * 64 + ni * 8 + (lane & 3) * 2;
            float b0 = sbias[col], b1 = sbias[col + 1];
            float2 o0 = make_float2(acc[mi][ni][0] + b0, acc[mi][ni][1] + b1);
            float2 o1 = make_float2(acc[mi][ni][2] + b0, acc[mi][ni][3] + b1);
            *(float2*)(C + (size_t)row0 * DIMc + nLoc + col) = o0;
            *(float2*)(C + (size_t)(row0 + 8) * DIMc + nLoc + col) = o1;
        }
    }
}

// ---------------------------------------------------------------------------
// fp16 2-term asymmetric GEMM (V, OUT): A = (hi, lo) fp16, W = single fp16.
// 128x256 tile, BK=32, 3-stage, 256 thr, 2x4 warps, 2 MMAs per tile pair.
// ---------------------------------------------------------------------------
__device__ __forceinline__ void issue2(
    uint32_t sbase, int t,
    const __half* __restrict__ Ah, const __half* __restrict__ Al,
    const __half* __restrict__ W, int bm, int nLoc, int kOff)
{
    #pragma unroll
    for (int j = 0; j < 8; j++) {
        int idx = t + j * 256;
        int r = idx >> 2, c = idx & 3;
        uint32_t so;
        const __half* src;
        if (r < 128)      { so = OFF2_AH; int rr = r;       src = Ah + (size_t)(bm + rr) * DIMc; so += (uint32_t)(rr * ROWB + c * 16); }
        else if (r < 256) { so = OFF2_AL; int rr = r - 128; src = Al + (size_t)(bm + rr) * DIMc; so += (uint32_t)(rr * ROWB + c * 16); }
        else              { so = OFF2_B;  int rr = r - 256; src = W  + (size_t)(nLoc + rr) * DIMc; so += (uint32_t)(rr * ROWB + c * 16); }
        CP16(sbase + so, src + kOff + c * 8);
    }
    CP_COMMIT();
}

__global__ void __launch_bounds__(256, 1) gemm_h2(
    const __half* __restrict__ Ah, const __half* __restrict__ Al,
    const __half* __restrict__ W, const float* __restrict__ bias,
    float* __restrict__ C)
{
    extern __shared__ __align__(16) char sm[];
    float* sbias = (float*)sm;
    uint32_t sb = smem_u32(sm) + 1024;

    int t = threadIdx.x;
    int wid = t >> 5, lane = t & 31;
    int warp_m = wid >> 2, warp_n = wid & 3;
    int bm = blockIdx.y << 7;
    int nLoc = blockIdx.x << 8;

    if (t < 256) sbias[t] = bias[nLoc + t];

    float acc[4][8][4];
    #pragma unroll
    for (int mi = 0; mi < 4; mi++)
        #pragma unroll
        for (int ni = 0; ni < 8; ni++)
            #pragma unroll
            for (int e = 0; e < 4; e++) acc[mi][ni][e] = 0.0f;

    uint32_t aoff = (uint32_t)((warp_m * 64 + (lane & 15)) * ROWB + (lane >> 4) * 16);
    uint32_t bpair = (uint32_t)((warp_n * 64 + (lane >> 4) * 8 + (lane & 7)) * ROWB
                                + ((lane >> 3) & 1) * 16);

    issue2(sb + 0 * STG2, t, Ah, Al, W, bm, nLoc, 0);
    issue2(sb + 1 * STG2, t, Ah, Al, W, bm, nLoc, 32);

    #pragma unroll 1
    for (int ch = 0; ch < 32; ch++) {
        CP_WAIT(1);
        __syncthreads();
        if (ch + 2 < 32)
            issue2(sb + ((ch + 2) % 3) * STG2, t, Ah, Al, W, bm, nLoc, (ch + 2) * 32);
        uint32_t stg = sb + (ch % 3) * STG2;
        #pragma unroll
        for (int ks = 0; ks < 2; ks++) {
            uint32_t ah[4][4], al[4][4], bb[8][2];
            #pragma unroll
            for (int mi = 0; mi < 4; mi++) {
                uint32_t a = stg + aoff + (uint32_t)(mi * 16 * ROWB + ks * 32);
                ldsm_x4(ah[mi], a + OFF2_AH);
                ldsm_x4(al[mi], a + OFF2_AL);
            }
            #pragma unroll
            for (int pni = 0; pni < 8; pni += 2) {
                uint32_t tmp[4];
                uint32_t b = stg + bpair + (uint32_t)(pni * 8 * ROWB + ks * 32);
                ldsm_x4(tmp, b + OFF2_B);
                bb[pni][0] = tmp[0]; bb[pni][1] = tmp[1];
                bb[pni + 1][0] = tmp[2]; bb[pni + 1][1] = tmp[3];
            }
            #pragma unroll
            for (int mi = 0; mi < 4; mi++)
                #pragma unroll
                for (int ni = 0; ni < 8; ni++) {
                    mma_f16(acc[mi][ni], ah[mi], bb[ni]);
                    mma_f16(acc[mi][ni], al[mi], bb[ni]);
                }
        }
        __syncthreads();
    }

    #pragma unroll
    for (int mi = 0; mi < 4; mi++) {
        int row0 = bm + warp_m * 64 + mi * 16 + (lane >> 2);
        #pragma unroll
        for (int ni = 0; ni < 8; ni++) {
            int col = warp_n * 64 + ni * 8 + (lane & 3) * 2;
            float b0 = sbias[col], b1 = sbias[col + 1];
            float2 o0 = make_float2(acc[mi][ni][0] + b0, acc[mi][ni][1] + b1);
            float2 o1 = make_float2(acc[mi][ni][2] + b0, acc[mi][ni][3] + b1);
            *(float2*)(C + (size_t)row0 * DIMc + nLoc + col) = o0;
            *(float2*)(C + (size_t)(row0 + 8) * DIMc + nLoc + col) = o1;
        }
    }
}

// ---------------------------------------------------------------------------
// Fused feature kernel: db-outer loop hoists W0 into registers.
// ---------------------------------------------------------------------------
#define W0P 68
#define FEAT_SMEM ((W0P * 64 + 4 * 64 * 64) * 4)   // 82,688 B

__global__ void __launch_bounds__(256) feature_kernel(const float* __restrict__ Wrf) {
    extern __shared__ float fs[];
    float* W0t = fs;
    float* ks  = fs + W0P * 64;
    float* qs  = ks + 4096;
    float* Vs  = qs + 4096;
    float* Es  = Vs + 4096;

    int bh = blockIdx.y;
    int b = bh >> 4, h = bh & 15;
    int l0 = blockIdx.x * 64;
    int t = threadIdx.x;

    for (int e = t; e < 4096; e += 256) {
        int d = e >> 6, f = e & 63;
        W0t[f * W0P + d] = Wrf[h * 4096 + e];
    }
    for (int e = t; e < 1024; e += 256) {
        int row = e >> 4, c4 = (e & 15) << 2;
        size_t g = (size_t)(b * Lseq + l0 + row) * DIMc + h * DHc + c4;
        *(float4*)(ks + row * 64 + c4) = *(const float4*)(g_k + g);
        *(float4*)(qs + row * 64 + c4) = *(const float4*)(g_q + g);
        *(float4*)(Vs + row * 64 + c4) = *(const float4*)(g_v + g);
    }
    __syncthreads();

    int warp = t >> 5, lane = t & 31;
    const float* w0p = W0t + lane * W0P;
    const float* w1p = W0t + (lane + 32) * W0P;
    int lb = warp * 8;

    float aK0[8], aK1[8], aQ0[8], aQ1[8], kk[8];
    #pragma unroll
    for (int r = 0; r < 8; r++) {
        aK0[r] = aK1[r] = aQ0[r] = aQ1[r] = kk[r] = 0.f;
    }

    #pragma unroll
    for (int db = 0; db < 16; db++) {
        float4 w0 = *(const float4*)(w0p + db * 4);
        float4 w1 = *(const float4*)(w1p + db * 4);
        #pragma unroll
        for (int r = 0; r < 8; r++) {
            float4 kv = *(const float4*)(ks + (lb + r) * 64 + db * 4);
            float4 qv = *(const float4*)(qs + (lb + r) * 64 + db * 4);
            aK0[r] = fmaf(kv.x, w0.x, aK0[r]); aK0[r] = fmaf(kv.y, w0.y, aK0[r]);
            aK0[r] = fmaf(kv.z, w0.z, aK0[r]); aK0[r] = fmaf(kv.w, w0.w, aK0[r]);
            aK1[r] = fmaf(kv.x, w1.x, aK1[r]); aK1[r] = fmaf(kv.y, w1.y, aK1[r]);
            aK1[r] = fmaf(kv.z, w1.z, aK1[r]); aK1[r] = fmaf(kv.w, w1.w, aK1[r]);
            aQ0[r] = fmaf(qv.x, w0.x, aQ0[r]); aQ0[r] = fmaf(qv.y, w0.y, aQ0[r]);
            aQ0[r] = fmaf(qv.z, w0.z, aQ0[r]); aQ0[r] = fmaf(qv.w, w0.w, aQ0[r]);
            aQ1[r] = fmaf(qv.x, w1.x, aQ1[r]); aQ1[r] = fmaf(qv.y, w1.y, aQ1[r]);
            aQ1[r] = fmaf(qv.z, w1.z, aQ1[r]); aQ1[r] = fmaf(qv.w, w1.w, aQ1[r]);
            kk[r]  = fmaf(kv.x, kv.x, kk[r]);  kk[r]  = fmaf(kv.y, kv.y, kk[r]);
            kk[r]  = fmaf(kv.z, kv.z, kk[r]);  kk[r]  = fmaf(kv.w, kv.w, kk[r]);
        }
    }

    #pragma unroll 1
    for (int r = 0; r < 8; r++) {
        int l = lb + r;
        float hk = 0.5f * kk[r];
        Es[l * 64 + lane]      = __expf(aK0[r] - hk);
        Es[l * 64 + lane + 32] = __expf(aK1[r] - hk);

        float e0 = __expf(aQ0[r]), e1 = __expf(aQ1[r]);
        float s = e0 + e1;
        #pragma unroll
        for (int o = 16; o > 0; o >>= 1)
            s += __shfl_xor_sync(0xffffffffu, s, o);
        float inv = 1.0f / s;
        size_t base = ((size_t)bh * Lseq + l0 + l) * NFc;
        g_phi[base + lane]      = e0 * inv;
        g_phi[base + lane + 32] = e1 * inv;
    }
    __syncthreads();

    int tf = (t >> 4) << 2;
    int td = (t & 15) << 2;
    float acc[4][4];
    #pragma unroll
    for (int i = 0; i < 4; i++)
        #pragma unroll
        for (int j = 0; j < 4; j++) acc[i][j] = 0.0f;
    float dacc[4] = {0.f, 0.f, 0.f, 0.f};

    #pragma unroll 4
    for (int l = 0; l < 64; l++) {
        float4 a  = *(const float4*)(Es + l * 64 + tf);
        float4 b4 = *(const float4*)(Vs + l * 64 + td);
        float av[4] = {a.x, a.y, a.z, a.w};
        float bv[4] = {b4.x, b4.y, b4.z, b4.w};
        #pragma unroll
        for (int i = 0; i < 4; i++)
            #pragma unroll
            for (int j = 0; j < 4; j++)
                acc[i][j] = fmaf(av[i], bv[j], acc[i][j]);
        if (td == 0) {
            #pragma unroll
            for (int i = 0; i < 4; i++) dacc[i] += av[i];
        }
    }

    #pragma unroll
    for (int i = 0; i < 4; i++)
        #pragma unroll
        for (int j = 0; j < 4; j++)
            atomicAdd(&g_Nt[bh * (DHc * NFc) + (td + j) * NFc + tf + i], acc[i][j]);
    if (td == 0) {
        #pragma unroll
        for (int i = 0; i < 4; i++)
            atomicAdd(&g_D[bh * NFc + tf + i], dacc[i]);
    }
}

// ---------------------------------------------------------------------------
// Combine: j-outer / r-inner (N cols in regs); writes ctx fp16 hi/lo planes.
// ---------------------------------------------------------------------------
__global__ void __launch_bounds__(256) combine_kernel() {
    int bh = blockIdx.y;
    int b = bh >> 4, h = bh & 15;
    int l0 = blockIdx.x * 64;

    __shared__ float Nts[64 * W0P];
    __shared__ float Ds[NFc];
    __shared__ float sSE;

    int t = threadIdx.x;
    for (int e = t; e < 4096; e += 256) {
        int d = e >> 6, f = e & 63;
        Nts[d * W0P + f] = g_Nt[bh * (DHc * NFc) + e];
    }
    if (t < NFc) Ds[t] = g_D[bh * NFc + t];
    __syncthreads();
    if (t == 0) {
        float s = 0.f;
        #pragma unroll
        for (int f = 0; f < NFc; f++) s += Ds[f];
        sSE = s * EPSf;
    }
    __syncthreads();

    int warp = t >> 5, lane = t & 31;
    const float* n0p = Nts + lane * W0P;
    const float* n1p = Nts + (lane + 32) * W0P;
    size_t lbase = (size_t)bh * Lseq + l0 + warp * 8;

    float num0[8], num1[8], den[8];
    #pragma unroll
    for (int r = 0; r < 8; r++) { num0[r] = num1[r] = den[r] = 0.f; }

    #pragma unroll 4
    for (int j = 0; j < 16; j++) {
        float4 n0 = *(const float4*)(n0p + j * 4);
        float4 n1 = *(const float4*)(n1p + j * 4);
        float4 dd = *(const float4*)(Ds + j * 4);
        #pragma unroll
        for (int r = 0; r < 8; r++) {
            float4 p = *(const float4*)(g_phi + (lbase + r) * NFc + j * 4);
            num0[r] = fmaf(p.x, n0.x, num0[r]); num0[r] = fmaf(p.y, n0.y, num0[r]);
            num0[r] = fmaf(p.z, n0.z, num0[r]); num0[r] = fmaf(p.w, n0.w, num0[r]);
            num1[r] = fmaf(p.x, n1.x, num1[r]); num1[r] = fmaf(p.y, n1.y, num1[r]);
            num1[r] = fmaf(p.z, n1.z, num1[r]); num1[r] = fmaf(p.w, n1.w, num1[r]);
            den[r]  = fmaf(p.x, dd.x, den[r]);  den[r]  = fmaf(p.y, dd.y, den[r]);
            den[r]  = fmaf(p.z, dd.z, den[r]);  den[r]  = fmaf(p.w, dd.w, den[r]);
        }
    }

    #pragma unroll
    for (int r = 0; r < 8; r++) {
        int l = l0 + warp * 8 + r;
        float invd = 1.0f / (den[r] + sSE);
        float v0 = num0[r] * invd;
        float v1 = num1[r] * invd;
        size_t g = (size_t)(b * Lseq + l) * DIMc + h * DHc;
        __half h0 = __float2half_rn(v0);
        __half h1 = __float2half_rn(v1);
        g_cth[g + lane]      = h0;
        g_cth[g + lane + 32] = h1;
        g_ctl[g + lane]      = __float2half_rn(v0 - __half2float(h0));
        g_ctl[g + lane + 32] = __float2half_rn(v1 - __half2float(h1));
    }
}

// ---------------------------------------------------------------------------
// Launch
// ---------------------------------------------------------------------------
extern "C" void kernel_launch(void* const* d_in, const int* in_sizes, int n_in,
                              void* d_out, int out_size) {
    const float* x   = (const float*)d_in[0];
    const float* Wq  = (const float*)d_in[1];
    const float* bq  = (const float*)d_in[2];
    const float* Wk  = (const float*)d_in[3];
    const float* bk  = (const float*)d_in[4];
    const float* Wv  = (const float*)d_in[5];
    const float* bv  = (const float*)d_in[6];
    const float* Wo  = (const float*)d_in[7];
    const float* bo  = (const float*)d_in[8];
    const float* Wrf = (const float*)d_in[9];
    float* out = (float*)d_out;

    float *q, *k, *v;
    __nv_bfloat16 *xhi, *xlo, *whi, *wlo;
    __half *xh, *xl, *cth, *ctl, *wv16, *wo16;
    cudaGetSymbolAddress((void**)&q,    g_q);
    cudaGetSymbolAddress((void**)&k,    g_k);
    cudaGetSymbolAddress((void**)&v,    g_v);
    cudaGetSymbolAddress((void**)&xhi,  g_xhi);
    cudaGetSymbolAddress((void**)&xlo,  g_xlo);
    cudaGetSymbolAddress((void**)&whi,  g_whi);
    cudaGetSymbolAddress((void**)&wlo,  g_wlo);
    cudaGetSymbolAddress((void**)&xh,   g_xh);
    cudaGetSymbolAddress((void**)&xl,   g_xl);
    cudaGetSymbolAddress((void**)&cth,  g_cth);
    cudaGetSymbolAddress((void**)&ctl,  g_ctl);
    cudaGetSymbolAddress((void**)&wv16, g_wv16);
    cudaGetSymbolAddress((void**)&wo16, g_wo16);

    cudaFuncSetAttribute(gemm_bf3, cudaFuncAttributeMaxDynamicSharedMemorySize, GEMM3_SMEM);
    cudaFuncSetAttribute(gemm_h2,  cudaFuncAttributeMaxDynamicSharedMemorySize, GEMM2_SMEM);
    cudaFuncSetAttribute(feature_kernel, cudaFuncAttributeMaxDynamicSharedMemorySize, FEAT_SMEM);

    const size_t WN = (size_t)DIMc * DIMc;
    const int xn4 = (int)(((size_t)Mrows * DIMc) / 4);
    const int wn4 = (int)(WN / 4);

    split_x<<<(xn4 + 255) / 256, 256>>>(x, xhi, xlo, xh, xl, xn4);
    split_w<<<(wn4 + 255) / 256, 256>>>(Wq, whi + 0 * WN, wlo + 0 * WN, wn4);
    split_w<<<(wn4 + 255) / 256, 256>>>(Wk, whi + 1 * WN, wlo + 1 * WN, wn4);
    conv_h<<<(wn4 + 255) / 256, 256>>>(Wv, wv16, wn4);
    conv_h<<<(wn4 + 255) / 256, 256>>>(Wo, wo16, wn4);

    init_kernel<<<(BHc * DHc * NFc + 255) / 256, 256>>>();

    // Q, K projections (bf16 3-term), fused: grid.x = 2 weights x 4 N-blocks
    {
        GemmArgs a;
        a.whi[0] = whi + 0 * WN; a.whi[1] = whi + 1 * WN;
        a.wlo[0] = wlo + 0 * WN; a.wlo[1] = wlo + 1 * WN;
        a.bias[0] = bq; a.bias[1] = bk;
        a.C[0] = q; a.C[1] = k;
        gemm_bf3<<<dim3(8, Mrows / 128), 256, GEMM3_SMEM>>>(xhi, xlo, a);
    }
    // V projection (fp16 2-term asym)
    gemm_h2<<<dim3(4, Mrows / 128), 256, GEMM2_SMEM>>>(xh, xl, wv16, bv, v);

    feature_kernel<<<dim3(Lseq / 64, BHc), 256, FEAT_SMEM>>>(Wrf);
    combine_kernel<<<dim3(Lseq / 64, BHc), 256>>>();

    // Output GEMM (fp16 2-term asym)
    gemm_h2<<<dim3(4, Mrows / 128), 256, GEMM2_SMEM>>>(cth, ctl, wo16, bo, out);
}